// round 8
// baseline (speedup 1.0000x reference)
#include <cuda_runtime.h>
#include <cuda_bf16.h>
#include <cstdint>

// ---------------- problem constants ----------------
#define NPTS  50000
#define HN    32
#define INF   128
#define MIDF  64
#define OUTF  256
#define KP    15
#define KPD   (KP*MIDF)      // 960
#define KPEXT 0.48f
#define BNEPS 1e-6f
#define SLOPE 0.1f

typedef unsigned long long ull;

// ---------------- packed f32x2 helpers ----------------
__device__ __forceinline__ ull pack2(float x, float y) {
    ull r; asm("mov.b64 %0, {%1, %2};" : "=l"(r) : "f"(x), "f"(y)); return r;
}
__device__ __forceinline__ void unpack2(ull v, float& x, float& y) {
    asm("mov.b64 {%0, %1}, %2;" : "=f"(x), "=f"(y) : "l"(v));
}
__device__ __forceinline__ void ffma2(ull& d, ull a, ull b) {
    asm("fma.rn.f32x2 %0, %1, %2, %0;" : "+l"(d) : "l"(a), "l"(b));
}

__device__ __forceinline__ uint32_t smem_u32(const void* p) {
    uint32_t a;
    asm("{ .reg .u64 t; cvta.to.shared.u64 t, %1; cvt.u32.u64 %0, t; }" : "=r"(a) : "l"(p));
    return a;
}

#define LDSM4(R, ADDR) \
    asm volatile("ldmatrix.sync.aligned.m8n8.x4.shared.b16 {%0,%1,%2,%3}, [%4];" \
        : "=r"((R)[0]), "=r"((R)[1]), "=r"((R)[2]), "=r"((R)[3]) : "r"(ADDR))

#define MMA16816(C, A, B0, B1) \
    asm volatile("mma.sync.aligned.m16n8k16.row.col.f32.bf16.bf16.f32 " \
        "{%0,%1,%2,%3}, {%4,%5,%6,%7}, {%8,%9}, {%0,%1,%2,%3};" \
        : "+f"((C)[0]), "+f"((C)[1]), "+f"((C)[2]), "+f"((C)[3]) \
        : "r"((A)[0]), "r"((A)[1]), "r"((A)[2]), "r"((A)[3]), "r"(B0), "r"(B1))

// hi/lo split of one float into packed bf16 halves
__device__ __forceinline__ void split_bf16(float x, unsigned short& h, unsigned short& l) {
    __nv_bfloat16 hb = __float2bfloat16(x);
    h = __bfloat16_as_ushort(hb);
    l = __bfloat16_as_ushort(__float2bfloat16(x - __bfloat162float(hb)));
}

// ---------------- scratch ----------------
__device__ __align__(16) float g_y1 [NPTS*MIDF];
__device__ __align__(16) float g_x2 [NPTS*MIDF];
__device__ __align__(16) float g_y3 [NPTS*OUTF];
__device__ __align__(16) float g_ysc[NPTS*OUTF];

__device__ __align__(16) __nv_bfloat16 g_wf_hi [NPTS*KPD], g_wf_lo [NPTS*KPD];
__device__ __align__(16) __nv_bfloat16 g_w1t_hi[MIDF*INF],  g_w1t_lo[MIDF*INF];
__device__ __align__(16) __nv_bfloat16 g_kwt_hi[MIDF*KPD],  g_kwt_lo[MIDF*KPD];
__device__ __align__(16) __nv_bfloat16 g_w3t_hi[OUTF*MIDF], g_w3t_lo[OUTF*MIDF];
__device__ __align__(16) __nv_bfloat16 g_wst_hi[OUTF*INF],  g_wst_lo[OUTF*INF];

__device__ __align__(16) float g_sum1[MIDF], g_sq1[MIDF], g_a1[MIDF], g_c1[MIDF];
__device__ __align__(16) float g_sum2[MIDF], g_sq2[MIDF], g_a2[MIDF], g_c2[MIDF];
__device__ __align__(16) float g_sum3[OUTF], g_sq3[OUTF], g_a3[OUTF], g_c3[OUTF];
__device__ __align__(16) float g_sumS[OUTF], g_sqS[OUTF], g_aS[OUTF], g_cS[OUTF];

// ---------------- small kernels ----------------
__global__ void zero_stats_kernel() {
    int t = threadIdx.x;
    if (t < MIDF) { g_sum1[t]=0.f; g_sq1[t]=0.f; g_sum2[t]=0.f; g_sq2[t]=0.f; }
    g_sum3[t]=0.f; g_sq3[t]=0.f; g_sumS[t]=0.f; g_sqS[t]=0.f;
}

__global__ void finalize_kernel(const float* __restrict__ gg,
                                const float* __restrict__ bb, int which) {
    int t = threadIdx.x;
    const float* sum; const float* sq; float* a; float* c;
    switch (which) {
        case 0:  sum=g_sum1; sq=g_sq1; a=g_a1; c=g_c1; break;
        case 1:  sum=g_sum2; sq=g_sq2; a=g_a2; c=g_c2; break;
        case 2:  sum=g_sum3; sq=g_sq3; a=g_a3; c=g_c3; break;
        default: sum=g_sumS; sq=g_sqS; a=g_aS; c=g_cS; break;
    }
    const float inv = 1.0f / (float)NPTS;
    float m = sum[t] * inv;
    float v = sq[t] * inv - m * m;
    float av = gg[t] * rsqrtf(v + BNEPS);
    a[t] = av;
    c[t] = fmaf(-m, av, bb[t]);
}

// transpose+split weights: src[K][N] -> dst[N][K]
__global__ void splitT_kernel(const float* __restrict__ src,
                              __nv_bfloat16* __restrict__ dh,
                              __nv_bfloat16* __restrict__ dl, int K, int N) {
    int i = blockIdx.x*blockDim.x + threadIdx.x;
    if (i >= K*N) return;
    int n = i / K;
    int k = i - n*K;
    float x = src[(size_t)k*N + n];
    __nv_bfloat16 h = __float2bfloat16(x);
    dh[i] = h;
    dl[i] = __float2bfloat16(x - __bfloat162float(h));
}

// ---------------- mma.sync bf16 GEMM with fused A conversion ----------------
// C[M,Ncol] = A[M,K] @ Bt[Ncol,K]^T, hi/lo split, 3 MMA passes per k16.
// Block 256 thr = 8 warps (4m x 2n), tile 128x64, K-chunk 32, padded smem.
// AMODE: 0 = A given as bf16 hi/lo pair
//        1 = A fp32, split on the fly
//        2 = A fp32, bn+lrelu (trA/trC) then split
// Software pipeline: STS(regs) -> sync -> LDG(next) -> MMA -> sync.
#define KC   32
#define KCP  40
template<int AMODE>
__global__ void __launch_bounds__(256) mma_gemm_kernel(
        const float* __restrict__ Af,
        const __nv_bfloat16* __restrict__ Ahi,
        const __nv_bfloat16* __restrict__ Alo,
        const __nv_bfloat16* __restrict__ Bhi,
        const __nv_bfloat16* __restrict__ Blo,
        const float* __restrict__ trA,
        const float* __restrict__ trC,
        float* __restrict__ C,
        float* __restrict__ cS, float* __restrict__ cQ,
        int Ktot, int Ncol) {
    __shared__ __align__(16) __nv_bfloat16 sAh[128][KCP];
    __shared__ __align__(16) __nv_bfloat16 sAl[128][KCP];
    __shared__ __align__(16) __nv_bfloat16 sBh[64][KCP];
    __shared__ __align__(16) __nv_bfloat16 sBl[64][KCP];

    const int tid  = threadIdx.x;
    const int wid  = tid >> 5;
    const int lane = tid & 31;
    const int wr   = wid & 3;
    const int wc   = wid >> 2;
    const int row0 = blockIdx.x * 128;
    const int col0 = blockIdx.y * 64;

    // loader coordinates
    const int ar    = tid >> 1;        // A row within tile
    const int ahalf = tid & 1;         // 16-element half of the 32-wide chunk
    const int agrow = row0 + ar;
    const bool aval = agrow < NPTS;
    const int br    = tid >> 2;        // B row within tile
    const int bj    = tid & 3;         // uint4 index (8 bf16)

    // prefetch registers
    float  aF[16];
    uint4  aH[2], aL[2];
    uint4  bH, bL;

    auto ldgA = [&](int ck) {
        if (AMODE == 0) {
            const uint4* sh = (const uint4*)(Ahi + (size_t)agrow*Ktot + ck*KC) + ahalf*2;
            const uint4* sl = (const uint4*)(Alo + (size_t)agrow*Ktot + ck*KC) + ahalf*2;
            #pragma unroll
            for (int j=0;j<2;j++) {
                aH[j] = aval ? sh[j] : make_uint4(0,0,0,0);
                aL[j] = aval ? sl[j] : make_uint4(0,0,0,0);
            }
        } else {
            const float4* sf = (const float4*)(Af + (size_t)agrow*Ktot + ck*KC) + ahalf*4;
            #pragma unroll
            for (int j=0;j<4;j++) {
                float4 t = aval ? sf[j] : make_float4(0.f,0.f,0.f,0.f);
                aF[j*4+0]=t.x; aF[j*4+1]=t.y; aF[j*4+2]=t.z; aF[j*4+3]=t.w;
            }
        }
    };
    auto ldgB = [&](int ck) {
        bH = *((const uint4*)(Bhi + (size_t)(col0 + br)*Ktot + ck*KC) + bj);
        bL = *((const uint4*)(Blo + (size_t)(col0 + br)*Ktot + ck*KC) + bj);
    };
    auto stsAB = [&](int ck) {
        if (AMODE == 0) {
            *(uint4*)&sAh[ar][ahalf*16]   = aH[0];
            *(uint4*)&sAh[ar][ahalf*16+8] = aH[1];
            *(uint4*)&sAl[ar][ahalf*16]   = aL[0];
            *(uint4*)&sAl[ar][ahalf*16+8] = aL[1];
        } else {
            uint32_t hw[8], lw[8];
            const int kc0 = ck*KC + ahalf*16;
            #pragma unroll
            for (int p=0;p<8;p++) {
                float x0 = aF[2*p], x1 = aF[2*p+1];
                if (AMODE == 2) {
                    x0 = fmaf(trA[kc0+2*p],   x0, trC[kc0+2*p]);   x0 = fmaxf(x0, SLOPE*x0);
                    x1 = fmaf(trA[kc0+2*p+1], x1, trC[kc0+2*p+1]); x1 = fmaxf(x1, SLOPE*x1);
                }
                unsigned short h0,l0,h1,l1;
                split_bf16(x0, h0, l0);
                split_bf16(x1, h1, l1);
                hw[p] = ((uint32_t)h1 << 16) | h0;
                lw[p] = ((uint32_t)l1 << 16) | l0;
            }
            *(uint4*)&sAh[ar][ahalf*16]   = make_uint4(hw[0],hw[1],hw[2],hw[3]);
            *(uint4*)&sAh[ar][ahalf*16+8] = make_uint4(hw[4],hw[5],hw[6],hw[7]);
            *(uint4*)&sAl[ar][ahalf*16]   = make_uint4(lw[0],lw[1],lw[2],lw[3]);
            *(uint4*)&sAl[ar][ahalf*16+8] = make_uint4(lw[4],lw[5],lw[6],lw[7]);
        }
        *(uint4*)&sBh[br][bj*8] = bH;
        *(uint4*)&sBl[br][bj*8] = bL;
    };

    float c[2][4][4];
    #pragma unroll
    for (int mb=0; mb<2; mb++)
        #pragma unroll
        for (int nb=0; nb<4; nb++)
            #pragma unroll
            for (int e=0; e<4; e++) c[mb][nb][e] = 0.f;

    const int nck = Ktot / KC;
    ldgA(0); ldgB(0);
    for (int ck = 0; ck < nck; ck++) {
        stsAB(ck);
        __syncthreads();
        if (ck+1 < nck) { ldgA(ck+1); ldgB(ck+1); }

        #pragma unroll
        for (int s = 0; s < 2; s++) {
            const int k0 = s*16;
            const int lrow = lane & 15;
            const int lcol = k0 + ((lane >> 4) << 3);
            uint32_t a_h[2][4], a_l[2][4], b_h[2][4], b_l[2][4];
            #pragma unroll
            for (int mb=0; mb<2; mb++) {
                int r = wr*32 + mb*16 + lrow;
                LDSM4(a_h[mb], smem_u32(&sAh[r][lcol]));
                LDSM4(a_l[mb], smem_u32(&sAl[r][lcol]));
            }
            #pragma unroll
            for (int g=0; g<2; g++) {
                int r = wc*32 + g*16 + lrow;
                LDSM4(b_h[g], smem_u32(&sBh[r][lcol]));
                LDSM4(b_l[g], smem_u32(&sBl[r][lcol]));
            }
            #pragma unroll
            for (int mb=0; mb<2; mb++) {
                #pragma unroll
                for (int nb=0; nb<4; nb++) {
                    int g = nb >> 1, h = nb & 1;
                    MMA16816(c[mb][nb], a_h[mb], b_h[g][h], b_h[g][h+2]);
                    MMA16816(c[mb][nb], a_h[mb], b_l[g][h], b_l[g][h+2]);
                    MMA16816(c[mb][nb], a_l[mb], b_h[g][h], b_h[g][h+2]);
                }
            }
        }
        __syncthreads();
    }

    // ---- epilogue: store + per-column (sum, sumsq) ----
    #pragma unroll
    for (int nb=0; nb<4; nb++) {
        int ncol = col0 + wc*32 + nb*8 + (lane & 3)*2;
        float s0=0.f,q0=0.f,s1=0.f,q1=0.f;
        #pragma unroll
        for (int mb=0; mb<2; mb++) {
            int m0 = row0 + wr*32 + mb*16 + (lane >> 2);
            bool vA = m0 < NPTS, vB = (m0+8) < NPTS;
            float v0 = c[mb][nb][0], v1 = c[mb][nb][1];
            float v2 = c[mb][nb][2], v3 = c[mb][nb][3];
            if (vA) {
                *(float2*)&C[(size_t)m0*Ncol + ncol] = make_float2(v0, v1);
                s0 += v0; q0 += v0*v0; s1 += v1; q1 += v1*v1;
            }
            if (vB) {
                *(float2*)&C[(size_t)(m0+8)*Ncol + ncol] = make_float2(v2, v3);
                s0 += v2; q0 += v2*v2; s1 += v3; q1 += v3*v3;
            }
        }
        #pragma unroll
        for (int o=16;o>=4;o>>=1) {
            s0 += __shfl_xor_sync(0xffffffffu, s0, o);
            q0 += __shfl_xor_sync(0xffffffffu, q0, o);
            s1 += __shfl_xor_sync(0xffffffffu, s1, o);
            q1 += __shfl_xor_sync(0xffffffffu, q1, o);
        }
        if ((lane >> 2) == 0) {
            atomicAdd(&cS[ncol],   s0);
            atomicAdd(&cQ[ncol],   q0);
            atomicAdd(&cS[ncol+1], s1);
            atomicAdd(&cQ[ncol+1], q1);
        }
    }
}

// ---------------- KPConv gather: warp == point, 2 channels/thread ----------------
#define PPB 8
__global__ void __launch_bounds__(256) kpconv_kernel(
                              const float* __restrict__ qpts,
                              const float* __restrict__ spts,
                              const int*   __restrict__ inds,
                              const float* __restrict__ kpts) {
    __shared__ __align__(16) float s_infl[PPB][HN*16];
    __shared__ __align__(16) float s_del[PPB][HN][3];
    __shared__ int   s_idx[PPB][HN];
    __shared__ float s_kp[KP*3];

    const int tid  = threadIdx.x;
    const int w    = tid >> 5;
    const int lane = tid & 31;
    const int n = blockIdx.x * PPB + w;

    if (tid < KP*3) s_kp[tid] = kpts[tid];

    {
        int idx = inds[n*HN + lane];
        s_idx[w][lane] = idx;
        s_del[w][lane][0] = spts[idx*3+0] - qpts[n*3+0];
        s_del[w][lane][1] = spts[idx*3+1] - qpts[n*3+1];
        s_del[w][lane][2] = spts[idx*3+2] - qpts[n*3+2];
    }
    __syncthreads();

    {
        int k  = lane & 15;
        int hb = (lane >> 4) << 4;
        bool valid = (k < KP);
        float kx=0.f, ky=0.f, kz=0.f;
        if (valid) { kx = s_kp[k*3+0]; ky = s_kp[k*3+1]; kz = s_kp[k*3+2]; }
        #pragma unroll 4
        for (int j = 0; j < 16; j++) {
            int h = hb + j;
            float val = 0.f;
            if (valid) {
                float dx = s_del[w][h][0] - kx;
                float dy = s_del[w][h][1] - ky;
                float dz = s_del[w][h][2] - kz;
                float sq = fmaf(dx,dx,fmaf(dy,dy,dz*dz));
                float dist = sqrtf(fmaxf(sq, 1e-12f));
                val = fmaxf(0.f, 1.f - dist*(1.f/KPEXT));
            }
            s_infl[w][h*16 + k] = val;
        }
    }
    __syncwarp();

    const int ch = lane*2;
    const float a1x = g_a1[ch], a1y = g_a1[ch+1];
    const float c1x = g_c1[ch], c1y = g_c1[ch+1];

    ull acc0[8], acc1[8];
    #pragma unroll
    for (int m=0;m<8;m++) { acc0[m]=0ull; acc1[m]=0ull; }

    const float* inflp = s_infl[w];
    #pragma unroll 2
    for (int h = 0; h < HN; h++) {
        int idx = s_idx[w][h];
        float2 v = *(const float2*)&g_y1[(size_t)idx*MIDF + ch];
        v.x = fmaf(a1x, v.x, c1x); v.x = fmaxf(v.x, SLOPE*v.x);
        v.y = fmaf(a1y, v.y, c1y); v.y = fmaxf(v.y, SLOPE*v.y);
        ull vx2 = pack2(v.x, v.x);
        ull vy2 = pack2(v.y, v.y);

        const ulonglong2* fp = (const ulonglong2*)&inflp[h*16];
        ulonglong2 fA = fp[0], fB = fp[1], fC = fp[2], fD = fp[3];
        ull fk2[8] = {fA.x,fA.y,fB.x,fB.y,fC.x,fC.y,fD.x,fD.y};
        #pragma unroll
        for (int m=0;m<8;m++) {
            ffma2(acc0[m], vx2, fk2[m]);
            ffma2(acc1[m], vy2, fk2[m]);
        }
    }

    size_t base = (size_t)n*KPD + ch;
    #pragma unroll
    for (int m=0;m<8;m++) {
        float x0,x1,y0,y1;
        unpack2(acc0[m], x0, x1);
        unpack2(acc1[m], y0, y1);
        {
            unsigned short hx,lx,hy,ly;
            split_bf16(x0, hx, lx);
            split_bf16(y0, hy, ly);
            *(uint32_t*)&g_wf_hi[base + (size_t)(2*m)*MIDF] = ((uint32_t)hy<<16)|hx;
            *(uint32_t*)&g_wf_lo[base + (size_t)(2*m)*MIDF] = ((uint32_t)ly<<16)|lx;
        }
        if (2*m+1 < KP) {
            unsigned short hx,lx,hy,ly;
            split_bf16(x1, hx, lx);
            split_bf16(y1, hy, ly);
            *(uint32_t*)&g_wf_hi[base + (size_t)(2*m+1)*MIDF] = ((uint32_t)hy<<16)|hx;
            *(uint32_t*)&g_wf_lo[base + (size_t)(2*m+1)*MIDF] = ((uint32_t)ly<<16)|lx;
        }
    }
}

// ---------------- final ----------------
__global__ void final_kernel(float* __restrict__ out) {
    int i = blockIdx.x*blockDim.x + threadIdx.x;
    const int total4 = NPTS*OUTF/4;
    if (i >= total4) return;
    int c0 = (i << 2) & (OUTF-1);
    float4 y = *(const float4*)&g_y3[(size_t)i*4];
    float4 s = *(const float4*)&g_ysc[(size_t)i*4];
    float vy[4] = {y.x,y.y,y.z,y.w};
    float vs[4] = {s.x,s.y,s.z,s.w};
    float vo[4];
    #pragma unroll
    for (int j=0;j<4;j++) {
        int c = c0 + j;
        float a = fmaf(g_a3[c], vy[j], g_c3[c]); a = fmaxf(a, SLOPE*a);
        float b = fmaf(g_aS[c], vs[j], g_cS[c]); b = fmaxf(b, SLOPE*b);
        float r = a + b;
        vo[j] = fmaxf(r, SLOPE*r);
    }
    *(float4*)&out[(size_t)i*4] = make_float4(vo[0],vo[1],vo[2],vo[3]);
}

// ---------------- launcher ----------------
extern "C" void kernel_launch(void* const* d_in, const int* in_sizes, int n_in,
                              void* d_out, int out_size) {
    const float* q    = (const float*)d_in[0];
    const float* s    = (const float*)d_in[1];
    const int*   inds = (const int*)  d_in[2];
    const float* feat = (const float*)d_in[3];
    const float* kp   = (const float*)d_in[4];
    const float* w1   = (const float*)d_in[5];
    const float* g1   = (const float*)d_in[6];
    const float* b1   = (const float*)d_in[7];
    const float* kw   = (const float*)d_in[8];
    const float* g2   = (const float*)d_in[9];
    const float* b2   = (const float*)d_in[10];
    const float* w3   = (const float*)d_in[11];
    const float* g3   = (const float*)d_in[12];
    const float* b3   = (const float*)d_in[13];
    const float* ws   = (const float*)d_in[14];
    const float* gs   = (const float*)d_in[15];
    const float* bs   = (const float*)d_in[16];
    float* out = (float*)d_out;

    float *p_y1, *p_x2, *p_y3, *p_ysc, *p_a2, *p_c2;
    float *p_sum1,*p_sq1,*p_sum2,*p_sq2,*p_sum3,*p_sq3,*p_sumS,*p_sqS;
    __nv_bfloat16 *p_wfh,*p_wfl;
    __nv_bfloat16 *p_w1h,*p_w1l,*p_kwh,*p_kwl,*p_w3h,*p_w3l,*p_wsh,*p_wsl;
    cudaGetSymbolAddress((void**)&p_y1,  g_y1);
    cudaGetSymbolAddress((void**)&p_x2,  g_x2);
    cudaGetSymbolAddress((void**)&p_y3,  g_y3);
    cudaGetSymbolAddress((void**)&p_ysc, g_ysc);
    cudaGetSymbolAddress((void**)&p_a2,  g_a2);
    cudaGetSymbolAddress((void**)&p_c2,  g_c2);
    cudaGetSymbolAddress((void**)&p_sum1, g_sum1); cudaGetSymbolAddress((void**)&p_sq1, g_sq1);
    cudaGetSymbolAddress((void**)&p_sum2, g_sum2); cudaGetSymbolAddress((void**)&p_sq2, g_sq2);
    cudaGetSymbolAddress((void**)&p_sum3, g_sum3); cudaGetSymbolAddress((void**)&p_sq3, g_sq3);
    cudaGetSymbolAddress((void**)&p_sumS, g_sumS); cudaGetSymbolAddress((void**)&p_sqS, g_sqS);
    cudaGetSymbolAddress((void**)&p_wfh, g_wf_hi);   cudaGetSymbolAddress((void**)&p_wfl, g_wf_lo);
    cudaGetSymbolAddress((void**)&p_w1h, g_w1t_hi);  cudaGetSymbolAddress((void**)&p_w1l, g_w1t_lo);
    cudaGetSymbolAddress((void**)&p_kwh, g_kwt_hi);  cudaGetSymbolAddress((void**)&p_kwl, g_kwt_lo);
    cudaGetSymbolAddress((void**)&p_w3h, g_w3t_hi);  cudaGetSymbolAddress((void**)&p_w3l, g_w3t_lo);
    cudaGetSymbolAddress((void**)&p_wsh, g_wst_hi);  cudaGetSymbolAddress((void**)&p_wsl, g_wst_lo);

    const int MT = (NPTS + 127) / 128;   // 391 row tiles

    zero_stats_kernel<<<1, 256>>>();

    // weight transposes + splits (small)
    splitT_kernel<<<(INF*MIDF  + 255)/256, 256>>>(w1, p_w1h, p_w1l, INF,  MIDF);
    splitT_kernel<<<(KPD*MIDF  + 255)/256, 256>>>(kw, p_kwh, p_kwl, KPD,  MIDF);
    splitT_kernel<<<(MIDF*OUTF + 255)/256, 256>>>(w3, p_w3h, p_w3l, MIDF, OUTF);
    splitT_kernel<<<(INF*OUTF  + 255)/256, 256>>>(ws, p_wsh, p_wsl, INF,  OUTF);

    // conv1: y1 = feat @ w1   (A fp32, split in-loader)
    mma_gemm_kernel<1><<<dim3(MT,1), 256>>>(feat, nullptr, nullptr, p_w1h, p_w1l,
                                            nullptr, nullptr, p_y1, p_sum1, p_sq1, INF, MIDF);
    finalize_kernel<<<1, MIDF>>>(g1, b1, 0);

    // KPConv gather -> wf (bf16 hi/lo)
    kpconv_kernel<<<NPTS/PPB, 256>>>(q, s, inds, kp);

    // conv2: x2 = wf @ kw   (A bf16 pair)
    mma_gemm_kernel<0><<<dim3(MT,1), 256>>>(nullptr, p_wfh, p_wfl, p_kwh, p_kwl,
                                            nullptr, nullptr, p_x2, p_sum2, p_sq2, KPD, MIDF);
    finalize_kernel<<<1, MIDF>>>(g2, b2, 1);

    // conv3: y3 = bn2lrelu(x2) @ w3   (A fp32 + transform)
    mma_gemm_kernel<2><<<dim3(MT,4), 256>>>(p_x2, nullptr, nullptr, p_w3h, p_w3l,
                                            p_a2, p_c2, p_y3, p_sum3, p_sq3, MIDF, OUTF);
    // shortcut: ysc = feat @ ws   (A fp32)
    mma_gemm_kernel<1><<<dim3(MT,4), 256>>>(feat, nullptr, nullptr, p_wsh, p_wsl,
                                            nullptr, nullptr, p_ysc, p_sumS, p_sqS, INF, OUTF);

    finalize_kernel<<<1, OUTF>>>(g3, b3, 2);
    finalize_kernel<<<1, OUTF>>>(gs, bs, 3);

    final_kernel<<<(NPTS*OUTF/4 + 255)/256, 256>>>(out);
}

// round 9
// speedup vs baseline: 1.0848x; 1.0848x over previous
#include <cuda_runtime.h>
#include <cuda_bf16.h>
#include <cstdint>

// ---------------- problem constants ----------------
#define NPTS  50000
#define HN    32
#define INF   128
#define MIDF  64
#define OUTF  256
#define KP    15
#define KPD   (KP*MIDF)      // 960
#define KPEXT 0.48f
#define BNEPS 1e-6f
#define SLOPE 0.1f

typedef unsigned long long ull;

// ---------------- packed f32x2 helpers ----------------
__device__ __forceinline__ ull pack2(float x, float y) {
    ull r; asm("mov.b64 %0, {%1, %2};" : "=l"(r) : "f"(x), "f"(y)); return r;
}
__device__ __forceinline__ void unpack2(ull v, float& x, float& y) {
    asm("mov.b64 {%0, %1}, %2;" : "=f"(x), "=f"(y) : "l"(v));
}
__device__ __forceinline__ void ffma2(ull& d, ull a, ull b) {
    asm("fma.rn.f32x2 %0, %1, %2, %0;" : "+l"(d) : "l"(a), "l"(b));
}

__device__ __forceinline__ uint32_t smem_u32(const void* p) {
    uint32_t a;
    asm("{ .reg .u64 t; cvta.to.shared.u64 t, %1; cvt.u32.u64 %0, t; }" : "=r"(a) : "l"(p));
    return a;
}

// 16B async copy, zero-fill when szbytes==0
__device__ __forceinline__ void cp_async16(uint32_t dst, const void* src, int szbytes) {
    asm volatile("cp.async.cg.shared.global [%0], [%1], 16, %2;"
                 :: "r"(dst), "l"(src), "r"(szbytes));
}
#define CP_COMMIT() asm volatile("cp.async.commit_group;" ::: "memory")
#define CP_WAIT1()  asm volatile("cp.async.wait_group 1;" ::: "memory")
#define CP_WAIT0()  asm volatile("cp.async.wait_group 0;" ::: "memory")

#define LDSM4(R, ADDR) \
    asm volatile("ldmatrix.sync.aligned.m8n8.x4.shared.b16 {%0,%1,%2,%3}, [%4];" \
        : "=r"((R)[0]), "=r"((R)[1]), "=r"((R)[2]), "=r"((R)[3]) : "r"(ADDR))

#define MMA16816(C, A, B0, B1) \
    asm volatile("mma.sync.aligned.m16n8k16.row.col.f32.bf16.bf16.f32 " \
        "{%0,%1,%2,%3}, {%4,%5,%6,%7}, {%8,%9}, {%0,%1,%2,%3};" \
        : "+f"((C)[0]), "+f"((C)[1]), "+f"((C)[2]), "+f"((C)[3]) \
        : "r"((A)[0]), "r"((A)[1]), "r"((A)[2]), "r"((A)[3]), "r"(B0), "r"(B1))

__device__ __forceinline__ void split_bf16(float x, unsigned short& h, unsigned short& l) {
    __nv_bfloat16 hb = __float2bfloat16(x);
    h = __bfloat16_as_ushort(hb);
    l = __bfloat16_as_ushort(__float2bfloat16(x - __bfloat162float(hb)));
}

// ---------------- scratch ----------------
__device__ __align__(16) float g_y1 [NPTS*MIDF];
__device__ __align__(16) float g_x2 [NPTS*MIDF];
__device__ __align__(16) float g_y3 [NPTS*OUTF];
__device__ __align__(16) float g_ysc[NPTS*OUTF];

__device__ __align__(16) __nv_bfloat16 g_feat_hi[NPTS*INF], g_feat_lo[NPTS*INF];
__device__ __align__(16) __nv_bfloat16 g_wf_hi [NPTS*KPD], g_wf_lo [NPTS*KPD];
__device__ __align__(16) __nv_bfloat16 g_x2t_hi[NPTS*MIDF], g_x2t_lo[NPTS*MIDF];
__device__ __align__(16) __nv_bfloat16 g_w1t_hi[MIDF*INF],  g_w1t_lo[MIDF*INF];
__device__ __align__(16) __nv_bfloat16 g_kwt_hi[MIDF*KPD],  g_kwt_lo[MIDF*KPD];
__device__ __align__(16) __nv_bfloat16 g_w3t_hi[OUTF*MIDF], g_w3t_lo[OUTF*MIDF];
__device__ __align__(16) __nv_bfloat16 g_wst_hi[OUTF*INF],  g_wst_lo[OUTF*INF];

__device__ __align__(16) float g_sum1[MIDF], g_sq1[MIDF], g_a1[MIDF], g_c1[MIDF];
__device__ __align__(16) float g_sum2[MIDF], g_sq2[MIDF], g_a2[MIDF], g_c2[MIDF];
__device__ __align__(16) float g_sum3[OUTF], g_sq3[OUTF], g_a3[OUTF], g_c3[OUTF];
__device__ __align__(16) float g_sumS[OUTF], g_sqS[OUTF], g_aS[OUTF], g_cS[OUTF];

// ---------------- prep: zero stats + all four weight transposes+splits ----
// segment sizes (elements of the transposed [N][K] outputs)
#define SEG1 (MIDF*INF)            // w1t   8192
#define SEG2 (MIDF*KPD)            // kwt  61440
#define SEG3 (OUTF*MIDF)           // w3t  16384
#define SEG4 (OUTF*INF)            // wst  32768
#define PREP_TOT (SEG1+SEG2+SEG3+SEG4)
__global__ void prep_kernel(const float* __restrict__ w1,
                            const float* __restrict__ kw,
                            const float* __restrict__ w3,
                            const float* __restrict__ ws) {
    int i = blockIdx.x*blockDim.x + threadIdx.x;
    if (i < MIDF) { g_sum1[i]=0.f; g_sq1[i]=0.f; g_sum2[i]=0.f; g_sq2[i]=0.f; }
    if (i < OUTF) { g_sum3[i]=0.f; g_sq3[i]=0.f; g_sumS[i]=0.f; g_sqS[i]=0.f; }
    if (i >= PREP_TOT) return;

    const float* src; __nv_bfloat16 *dh, *dl; int K, N, idx;
    if (i < SEG1)                { src=w1; dh=g_w1t_hi; dl=g_w1t_lo; K=INF;  N=MIDF; idx=i; }
    else if (i < SEG1+SEG2)      { src=kw; dh=g_kwt_hi; dl=g_kwt_lo; K=KPD;  N=MIDF; idx=i-SEG1; }
    else if (i < SEG1+SEG2+SEG3) { src=w3; dh=g_w3t_hi; dl=g_w3t_lo; K=MIDF; N=OUTF; idx=i-SEG1-SEG2; }
    else                         { src=ws; dh=g_wst_hi; dl=g_wst_lo; K=INF;  N=OUTF; idx=i-SEG1-SEG2-SEG3; }
    int n = idx / K;
    int k = idx - n*K;
    float x = src[(size_t)k*N + n];
    __nv_bfloat16 h = __float2bfloat16(x);
    dh[idx] = h;
    dl[idx] = __float2bfloat16(x - __bfloat162float(h));
}

__global__ void split_feat_kernel(const float* __restrict__ src) {
    int i = blockIdx.x*blockDim.x + threadIdx.x;
    if (i >= NPTS*INF) return;
    float x = src[i];
    __nv_bfloat16 h = __float2bfloat16(x);
    g_feat_hi[i] = h;
    g_feat_lo[i] = __float2bfloat16(x - __bfloat162float(h));
}

__global__ void finalize_kernel(const float* __restrict__ gg,
                                const float* __restrict__ bb, int which) {
    int t = threadIdx.x;
    const float* sum; const float* sq; float* a; float* c;
    switch (which) {
        case 0:  sum=g_sum1; sq=g_sq1; a=g_a1; c=g_c1; break;
        case 1:  sum=g_sum2; sq=g_sq2; a=g_a2; c=g_c2; break;
        case 2:  sum=g_sum3; sq=g_sq3; a=g_a3; c=g_c3; break;
        default: sum=g_sumS; sq=g_sqS; a=g_aS; c=g_cS; break;
    }
    const float inv = 1.0f / (float)NPTS;
    float m = sum[t] * inv;
    float v = sq[t] * inv - m * m;
    float av = gg[t] * rsqrtf(v + BNEPS);
    a[t] = av;
    c[t] = fmaf(-m, av, bb[t]);
}

__global__ void split_x2t_kernel() {
    int i = blockIdx.x*blockDim.x + threadIdx.x;
    if (i >= NPTS*MIDF) return;
    int c = i & (MIDF-1);
    float x = g_x2[i];
    float v = fmaf(g_a2[c], x, g_c2[c]);
    v = fmaxf(v, SLOPE*v);
    __nv_bfloat16 h = __float2bfloat16(v);
    g_x2t_hi[i] = h;
    g_x2t_lo[i] = __float2bfloat16(v - __bfloat162float(h));
}

// ---------------- mma.sync bf16 GEMM, cp.async double-buffered ----------------
// C[M,Ncol] = A[M,K] @ Bt[Ncol,K]^T, hi/lo split (3 MMA passes / k16).
// Block 256 thr = 8 warps (4m x 2n), tile 128x64, K-chunk 32, 2-stage smem.
#define KC   32
#define KCP  40
__global__ void __launch_bounds__(256) mma_gemm_kernel(
        const __nv_bfloat16* __restrict__ Ahi,
        const __nv_bfloat16* __restrict__ Alo,
        const __nv_bfloat16* __restrict__ Bhi,
        const __nv_bfloat16* __restrict__ Blo,
        float* __restrict__ C,
        float* __restrict__ cS, float* __restrict__ cQ,
        int Ktot, int Ncol) {
    __shared__ __align__(16) __nv_bfloat16 sAh[2][128][KCP];
    __shared__ __align__(16) __nv_bfloat16 sAl[2][128][KCP];
    __shared__ __align__(16) __nv_bfloat16 sBh[2][64][KCP];
    __shared__ __align__(16) __nv_bfloat16 sBl[2][64][KCP];

    const int tid  = threadIdx.x;
    const int wid  = tid >> 5;
    const int lane = tid & 31;
    const int wr   = wid & 3;
    const int wc   = wid >> 2;
    const int row0 = blockIdx.x * 128;
    const int col0 = blockIdx.y * 64;

    // issue one stage of async copies
    auto issue = [&](int ck, int st) {
        // A: 128 rows x 32 bf16 (hi+lo); 512 16B chunks each -> 2 per thread
        #pragma unroll
        for (int j = 0; j < 2; j++) {
            int c   = tid + 256*j;
            int r   = c >> 2;
            int seg = c & 3;
            int grow = row0 + r;
            int sz = (grow < NPTS) ? 16 : 0;
            int gr = (grow < NPTS) ? grow : 0;
            const __nv_bfloat16* srcH = Ahi + (size_t)gr*Ktot + ck*KC + seg*8;
            const __nv_bfloat16* srcL = Alo + (size_t)gr*Ktot + ck*KC + seg*8;
            cp_async16(smem_u32(&sAh[st][r][seg*8]), srcH, sz);
            cp_async16(smem_u32(&sAl[st][r][seg*8]), srcL, sz);
        }
        // B: 64 rows x 32 bf16 (hi+lo); 256 chunks each -> 1 per thread
        {
            int r   = tid >> 2;
            int seg = tid & 3;
            const __nv_bfloat16* srcH = Bhi + (size_t)(col0 + r)*Ktot + ck*KC + seg*8;
            const __nv_bfloat16* srcL = Blo + (size_t)(col0 + r)*Ktot + ck*KC + seg*8;
            cp_async16(smem_u32(&sBh[st][r][seg*8]), srcH, 16);
            cp_async16(smem_u32(&sBl[st][r][seg*8]), srcL, 16);
        }
        CP_COMMIT();
    };

    float c[2][4][4];
    #pragma unroll
    for (int mb=0; mb<2; mb++)
        #pragma unroll
        for (int nb=0; nb<4; nb++)
            #pragma unroll
            for (int e=0; e<4; e++) c[mb][nb][e] = 0.f;

    const int nck = Ktot / KC;
    issue(0, 0);
    for (int ck = 0; ck < nck; ck++) {
        const int st = ck & 1;
        if (ck+1 < nck) { issue(ck+1, st^1); CP_WAIT1(); }
        else            { CP_WAIT0(); }
        __syncthreads();

        #pragma unroll
        for (int s = 0; s < 2; s++) {
            const int k0 = s*16;
            const int lrow = lane & 15;
            const int lcol = k0 + ((lane >> 4) << 3);
            uint32_t a_h[2][4], a_l[2][4], b_h[2][4], b_l[2][4];
            #pragma unroll
            for (int mb=0; mb<2; mb++) {
                int r = wr*32 + mb*16 + lrow;
                LDSM4(a_h[mb], smem_u32(&sAh[st][r][lcol]));
                LDSM4(a_l[mb], smem_u32(&sAl[st][r][lcol]));
            }
            #pragma unroll
            for (int g=0; g<2; g++) {
                int r = wc*32 + g*16 + lrow;
                LDSM4(b_h[g], smem_u32(&sBh[st][r][lcol]));
                LDSM4(b_l[g], smem_u32(&sBl[st][r][lcol]));
            }
            #pragma unroll
            for (int mb=0; mb<2; mb++) {
                #pragma unroll
                for (int nb=0; nb<4; nb++) {
                    int g = nb >> 1, h = nb & 1;
                    MMA16816(c[mb][nb], a_h[mb], b_h[g][h], b_h[g][h+2]);
                    MMA16816(c[mb][nb], a_h[mb], b_l[g][h], b_l[g][h+2]);
                    MMA16816(c[mb][nb], a_l[mb], b_h[g][h], b_h[g][h+2]);
                }
            }
        }
        __syncthreads();
    }

    // ---- epilogue: store + per-column (sum, sumsq) ----
    #pragma unroll
    for (int nb=0; nb<4; nb++) {
        int ncol = col0 + wc*32 + nb*8 + (lane & 3)*2;
        float s0=0.f,q0=0.f,s1=0.f,q1=0.f;
        #pragma unroll
        for (int mb=0; mb<2; mb++) {
            int m0 = row0 + wr*32 + mb*16 + (lane >> 2);
            bool vA = m0 < NPTS, vB = (m0+8) < NPTS;
            float v0 = c[mb][nb][0], v1 = c[mb][nb][1];
            float v2 = c[mb][nb][2], v3 = c[mb][nb][3];
            if (vA) {
                *(float2*)&C[(size_t)m0*Ncol + ncol] = make_float2(v0, v1);
                s0 += v0; q0 += v0*v0; s1 += v1; q1 += v1*v1;
            }
            if (vB) {
                *(float2*)&C[(size_t)(m0+8)*Ncol + ncol] = make_float2(v2, v3);
                s0 += v2; q0 += v2*v2; s1 += v3; q1 += v3*v3;
            }
        }
        #pragma unroll
        for (int o=16;o>=4;o>>=1) {
            s0 += __shfl_xor_sync(0xffffffffu, s0, o);
            q0 += __shfl_xor_sync(0xffffffffu, q0, o);
            s1 += __shfl_xor_sync(0xffffffffu, s1, o);
            q1 += __shfl_xor_sync(0xffffffffu, q1, o);
        }
        if ((lane >> 2) == 0) {
            atomicAdd(&cS[ncol],   s0);
            atomicAdd(&cQ[ncol],   q0);
            atomicAdd(&cS[ncol+1], s1);
            atomicAdd(&cQ[ncol+1], q1);
        }
    }
}

// ---------------- KPConv gather: warp == point, 2 channels/thread ----------------
#define PPB 8
__global__ void __launch_bounds__(256) kpconv_kernel(
                              const float* __restrict__ qpts,
                              const float* __restrict__ spts,
                              const int*   __restrict__ inds,
                              const float* __restrict__ kpts) {
    __shared__ __align__(16) float s_infl[PPB][HN*16];
    __shared__ __align__(16) float s_del[PPB][HN][3];
    __shared__ int   s_idx[PPB][HN];
    __shared__ float s_kp[KP*3];

    const int tid  = threadIdx.x;
    const int w    = tid >> 5;
    const int lane = tid & 31;
    const int n = blockIdx.x * PPB + w;

    if (tid < KP*3) s_kp[tid] = kpts[tid];

    {
        int idx = inds[n*HN + lane];
        s_idx[w][lane] = idx;
        s_del[w][lane][0] = spts[idx*3+0] - qpts[n*3+0];
        s_del[w][lane][1] = spts[idx*3+1] - qpts[n*3+1];
        s_del[w][lane][2] = spts[idx*3+2] - qpts[n*3+2];
    }
    __syncthreads();

    {
        int k  = lane & 15;
        int hb = (lane >> 4) << 4;
        bool valid = (k < KP);
        float kx=0.f, ky=0.f, kz=0.f;
        if (valid) { kx = s_kp[k*3+0]; ky = s_kp[k*3+1]; kz = s_kp[k*3+2]; }
        #pragma unroll 4
        for (int j = 0; j < 16; j++) {
            int h = hb + j;
            float val = 0.f;
            if (valid) {
                float dx = s_del[w][h][0] - kx;
                float dy = s_del[w][h][1] - ky;
                float dz = s_del[w][h][2] - kz;
                float sq = fmaf(dx,dx,fmaf(dy,dy,dz*dz));
                float dist = sqrtf(fmaxf(sq, 1e-12f));
                val = fmaxf(0.f, 1.f - dist*(1.f/KPEXT));
            }
            s_infl[w][h*16 + k] = val;
        }
    }
    __syncwarp();

    const int ch = lane*2;
    const float a1x = g_a1[ch], a1y = g_a1[ch+1];
    const float c1x = g_c1[ch], c1y = g_c1[ch+1];

    ull acc0[8], acc1[8];
    #pragma unroll
    for (int m=0;m<8;m++) { acc0[m]=0ull; acc1[m]=0ull; }

    const float* inflp = s_infl[w];
    #pragma unroll 2
    for (int h = 0; h < HN; h++) {
        int idx = s_idx[w][h];
        float2 v = *(const float2*)&g_y1[(size_t)idx*MIDF + ch];
        v.x = fmaf(a1x, v.x, c1x); v.x = fmaxf(v.x, SLOPE*v.x);
        v.y = fmaf(a1y, v.y, c1y); v.y = fmaxf(v.y, SLOPE*v.y);
        ull vx2 = pack2(v.x, v.x);
        ull vy2 = pack2(v.y, v.y);

        const ulonglong2* fp = (const ulonglong2*)&inflp[h*16];
        ulonglong2 fA = fp[0], fB = fp[1], fC = fp[2], fD = fp[3];
        ull fk2[8] = {fA.x,fA.y,fB.x,fB.y,fC.x,fC.y,fD.x,fD.y};
        #pragma unroll
        for (int m=0;m<8;m++) {
            ffma2(acc0[m], vx2, fk2[m]);
            ffma2(acc1[m], vy2, fk2[m]);
        }
    }

    size_t base = (size_t)n*KPD + ch;
    #pragma unroll
    for (int m=0;m<8;m++) {
        float x0,x1,y0,y1;
        unpack2(acc0[m], x0, x1);
        unpack2(acc1[m], y0, y1);
        {
            unsigned short hx,lx,hy,ly;
            split_bf16(x0, hx, lx);
            split_bf16(y0, hy, ly);
            *(uint32_t*)&g_wf_hi[base + (size_t)(2*m)*MIDF] = ((uint32_t)hy<<16)|hx;
            *(uint32_t*)&g_wf_lo[base + (size_t)(2*m)*MIDF] = ((uint32_t)ly<<16)|lx;
        }
        if (2*m+1 < KP) {
            unsigned short hx,lx,hy,ly;
            split_bf16(x1, hx, lx);
            split_bf16(y1, hy, ly);
            *(uint32_t*)&g_wf_hi[base + (size_t)(2*m+1)*MIDF] = ((uint32_t)hy<<16)|hx;
            *(uint32_t*)&g_wf_lo[base + (size_t)(2*m+1)*MIDF] = ((uint32_t)ly<<16)|lx;
        }
    }
}

// ---------------- final ----------------
__global__ void final_kernel(float* __restrict__ out) {
    int i = blockIdx.x*blockDim.x + threadIdx.x;
    const int total4 = NPTS*OUTF/4;
    if (i >= total4) return;
    int c0 = (i << 2) & (OUTF-1);
    float4 y = *(const float4*)&g_y3[(size_t)i*4];
    float4 s = *(const float4*)&g_ysc[(size_t)i*4];
    float vy[4] = {y.x,y.y,y.z,y.w};
    float vs[4] = {s.x,s.y,s.z,s.w};
    float vo[4];
    #pragma unroll
    for (int j=0;j<4;j++) {
        int c = c0 + j;
        float a = fmaf(g_a3[c], vy[j], g_c3[c]); a = fmaxf(a, SLOPE*a);
        float b = fmaf(g_aS[c], vs[j], g_cS[c]); b = fmaxf(b, SLOPE*b);
        float r = a + b;
        vo[j] = fmaxf(r, SLOPE*r);
    }
    *(float4*)&out[(size_t)i*4] = make_float4(vo[0],vo[1],vo[2],vo[3]);
}

// ---------------- launcher ----------------
extern "C" void kernel_launch(void* const* d_in, const int* in_sizes, int n_in,
                              void* d_out, int out_size) {
    const float* q    = (const float*)d_in[0];
    const float* s    = (const float*)d_in[1];
    const int*   inds = (const int*)  d_in[2];
    const float* feat = (const float*)d_in[3];
    const float* kp   = (const float*)d_in[4];
    const float* w1   = (const float*)d_in[5];
    const float* g1   = (const float*)d_in[6];
    const float* b1   = (const float*)d_in[7];
    const float* kw   = (const float*)d_in[8];
    const float* g2   = (const float*)d_in[9];
    const float* b2   = (const float*)d_in[10];
    const float* w3   = (const float*)d_in[11];
    const float* g3   = (const float*)d_in[12];
    const float* b3   = (const float*)d_in[13];
    const float* ws   = (const float*)d_in[14];
    const float* gs   = (const float*)d_in[15];
    const float* bs   = (const float*)d_in[16];
    float* out = (float*)d_out;

    float *p_y1, *p_x2, *p_y3, *p_ysc;
    float *p_sum1,*p_sq1,*p_sum2,*p_sq2,*p_sum3,*p_sq3,*p_sumS,*p_sqS;
    __nv_bfloat16 *p_fh,*p_fl,*p_wfh,*p_wfl,*p_x2h,*p_x2l;
    __nv_bfloat16 *p_w1h,*p_w1l,*p_kwh,*p_kwl,*p_w3h,*p_w3l,*p_wsh,*p_wsl;
    cudaGetSymbolAddress((void**)&p_y1,  g_y1);
    cudaGetSymbolAddress((void**)&p_x2,  g_x2);
    cudaGetSymbolAddress((void**)&p_y3,  g_y3);
    cudaGetSymbolAddress((void**)&p_ysc, g_ysc);
    cudaGetSymbolAddress((void**)&p_sum1, g_sum1); cudaGetSymbolAddress((void**)&p_sq1, g_sq1);
    cudaGetSymbolAddress((void**)&p_sum2, g_sum2); cudaGetSymbolAddress((void**)&p_sq2, g_sq2);
    cudaGetSymbolAddress((void**)&p_sum3, g_sum3); cudaGetSymbolAddress((void**)&p_sq3, g_sq3);
    cudaGetSymbolAddress((void**)&p_sumS, g_sumS); cudaGetSymbolAddress((void**)&p_sqS, g_sqS);
    cudaGetSymbolAddress((void**)&p_fh,  g_feat_hi); cudaGetSymbolAddress((void**)&p_fl,  g_feat_lo);
    cudaGetSymbolAddress((void**)&p_wfh, g_wf_hi);   cudaGetSymbolAddress((void**)&p_wfl, g_wf_lo);
    cudaGetSymbolAddress((void**)&p_x2h, g_x2t_hi);  cudaGetSymbolAddress((void**)&p_x2l, g_x2t_lo);
    cudaGetSymbolAddress((void**)&p_w1h, g_w1t_hi);  cudaGetSymbolAddress((void**)&p_w1l, g_w1t_lo);
    cudaGetSymbolAddress((void**)&p_kwh, g_kwt_hi);  cudaGetSymbolAddress((void**)&p_kwl, g_kwt_lo);
    cudaGetSymbolAddress((void**)&p_w3h, g_w3t_hi);  cudaGetSymbolAddress((void**)&p_w3l, g_w3t_lo);
    cudaGetSymbolAddress((void**)&p_wsh, g_wst_hi);  cudaGetSymbolAddress((void**)&p_wsl, g_wst_lo);

    const int MT = (NPTS + 127) / 128;   // 391 row tiles

    // launch order chosen so launch #6 (ncu -s 5 -c 1) is GEMM2
    prep_kernel<<<(PREP_TOT + 255)/256, 256>>>(w1, kw, w3, ws);              // 1
    split_feat_kernel<<<(NPTS*INF + 255)/256, 256>>>(feat);                  // 2

    // conv1: y1 = feat @ w1
    mma_gemm_kernel<<<dim3(MT,1), 256>>>(p_fh, p_fl, p_w1h, p_w1l,
                                         p_y1, p_sum1, p_sq1, INF, MIDF);    // 3
    finalize_kernel<<<1, MIDF>>>(g1, b1, 0);                                 // 4

    // KPConv gather -> wf (bf16 hi/lo)
    kpconv_kernel<<<NPTS/PPB, 256>>>(q, s, inds, kp);                        // 5

    // conv2: x2 = wf @ kw
    mma_gemm_kernel<<<dim3(MT,1), 256>>>(p_wfh, p_wfl, p_kwh, p_kwl,
                                         p_x2, p_sum2, p_sq2, KPD, MIDF);    // 6 <- ncu
    finalize_kernel<<<1, MIDF>>>(g2, b2, 1);

    // bn2+lrelu+split
    split_x2t_kernel<<<(NPTS*MIDF + 255)/256, 256>>>();

    // conv3: y3 = x2t @ w3
    mma_gemm_kernel<<<dim3(MT,4), 256>>>(p_x2h, p_x2l, p_w3h, p_w3l,
                                         p_y3, p_sum3, p_sq3, MIDF, OUTF);
    // shortcut: ysc = feat @ ws
    mma_gemm_kernel<<<dim3(MT,4), 256>>>(p_fh, p_fl, p_wsh, p_wsl,
                                         p_ysc, p_sumS, p_sqS, INF, OUTF);

    finalize_kernel<<<1, OUTF>>>(g3, b3, 2);
    finalize_kernel<<<1, OUTF>>>(gs, bs, 3);

    final_kernel<<<(NPTS*OUTF/4 + 255)/256, 256>>>(out);
}